// round 8
// baseline (speedup 1.0000x reference)
#include <cuda_runtime.h>
#include <cuda_fp16.h>
#include <cstdint>

// ============================================================================
// Problem constants
// ============================================================================
#define NQ        1024
#define DDIM      512
#define MROWS     262144
#define BANK_TILE 128          // rows per CTA = TROWS (tensor) + 16 (ffma)
#define TROWS     112
#define MEGA      128          // queries per pass
#define NPASS     8
#define KCH       8            // k-chunks of 64 dims per pass
#define NCHUNK    64
#define THREADS   384

// smem layout. Row pads: 8-row ldmatrix strides hit distinct 16B groups.
#define BANK_RS    1040
#define QBUF_RS    144
#define SMEM_BANK  0
#define BANK_SZ    (BANK_TILE * BANK_RS)          // 133120
#define SMEM_QBUF  BANK_SZ
#define QBUF_SZ    (MEGA * QBUF_RS)               // 18432
#define SMEM_TOTAL (SMEM_QBUF + 3 * QBUF_SZ)      // 188416

__device__ __align__(1024) __half g_qh[NQ * DDIM];
__device__ unsigned g_key[NQ];

// ============================================================================
// Helpers
// ============================================================================
__device__ __forceinline__ uint32_t smem_to_u32(const void* p) {
    uint32_t a;
    asm("{ .reg .u64 t; cvta.to.shared.u64 t, %1; cvt.u32.u64 %0, t; }" : "=r"(a) : "l"(p));
    return a;
}

#define CP_ASYNC16(dst_u32, src_gptr) \
    asm volatile("cp.async.cg.shared.global [%0], [%1], 16;" :: "r"(dst_u32), "l"(src_gptr) : "memory")
#define CP_ASYNC_COMMIT() asm volatile("cp.async.commit_group;" ::: "memory")
#define CP_ASYNC_WAIT(n)  asm volatile("cp.async.wait_group %0;" :: "n"(n) : "memory")
#define BAR384()          asm volatile("bar.sync 0, %0;" :: "n"(THREADS) : "memory")

#define LDMATRIX_X4(r0, r1, r2, r3, addr) \
    asm volatile("ldmatrix.sync.aligned.m8n8.x4.shared.b16 {%0,%1,%2,%3}, [%4];" \
        : "=r"(r0), "=r"(r1), "=r"(r2), "=r"(r3) : "r"(addr))
#define LDMATRIX_X4T(r0, r1, r2, r3, addr) \
    asm volatile("ldmatrix.sync.aligned.m8n8.x4.trans.shared.b16 {%0,%1,%2,%3}, [%4];" \
        : "=r"(r0), "=r"(r1), "=r"(r2), "=r"(r3) : "r"(addr))

__device__ __forceinline__ void mma16816h(uint32_t* d, const uint32_t* a, uint32_t b0, uint32_t b1) {
    asm volatile(
        "mma.sync.aligned.m16n8k16.row.col.f16.f16.f16.f16 "
        "{%0,%1}, {%2,%3,%4,%5}, {%6,%7}, {%0,%1};"
        : "+r"(d[0]), "+r"(d[1])
        : "r"(a[0]), "r"(a[1]), "r"(a[2]), "r"(a[3]), "r"(b0), "r"(b1));
}

__device__ __forceinline__ __half2 u2h2(uint32_t u) { return *reinterpret_cast<__half2*>(&u); }
__device__ __forceinline__ uint32_t h22u(__half2 h) { return *reinterpret_cast<uint32_t*>(&h); }

__device__ __forceinline__ unsigned enc_key(float f) {
    unsigned b = __float_as_uint(f);
    return (b & 0x80000000u) ? ~b : (b | 0x80000000u);
}

// cp.async loader: chunk j = pass*8 + kc (128 queries x 64 fp16 dims) -> slot
__device__ __forceinline__ void issue_qchunk(uint32_t sb, int tid, int j, int slot) {
    const int pass = j >> 3, kc = j & 7;
    const char* src_base = reinterpret_cast<const char*>(g_qh)
                         + (size_t)(pass * MEGA) * (DDIM * 2) + kc * 128;
    const uint32_t dst_base = sb + (uint32_t)(SMEM_QBUF + slot * QBUF_SZ);
    #pragma unroll
    for (int it = 0; it < 3; ++it) {
        int idx = tid + it * THREADS;          // 1024 granules of 16B
        if (idx < 1024) {
            int n = idx >> 3, t = idx & 7;
            CP_ASYNC16(dst_base + (uint32_t)(n * QBUF_RS + t * 16),
                       src_base + (size_t)n * (DDIM * 2) + t * 16);
        }
    }
    CP_ASYNC_COMMIT();
}

// ============================================================================
// Kernel 1: normalize queries -> fp16 buffer; init max keys
// ============================================================================
__global__ void __launch_bounds__(128) prep_kernel(const float* __restrict__ feat) {
    const int warp = threadIdx.x >> 5;
    const int lane = threadIdx.x & 31;
    const int b    = blockIdx.x * 4 + warp;
    const float4* src = reinterpret_cast<const float4*>(feat + (size_t)b * DDIM);

    float4 v[4];
    float ss = 0.0f;
    #pragma unroll
    for (int p = 0; p < 4; ++p) {
        v[p] = src[p * 32 + lane];
        ss += v[p].x * v[p].x + v[p].y * v[p].y + v[p].z * v[p].z + v[p].w * v[p].w;
    }
    #pragma unroll
    for (int o = 16; o > 0; o >>= 1) ss += __shfl_xor_sync(0xFFFFFFFFu, ss, o);
    const float inv = rsqrtf(ss);

    __half2* dst = reinterpret_cast<__half2*>(g_qh + (size_t)b * DDIM);
    #pragma unroll
    for (int p = 0; p < 4; ++p) {
        dst[(p * 32 + lane) * 2 + 0] = __floats2half2_rn(v[p].x * inv, v[p].y * inv);
        dst[(p * 32 + lane) * 2 + 1] = __floats2half2_rn(v[p].z * inv, v[p].w * inv);
    }
    if (lane == 0) g_key[b] = 0u;
}

// ============================================================================
// Tensor warps: warp tile m32 x (NBT*16), fp16 accum. NBT=4 (rows 0-63) or
// NBT=3 (rows 64-111). One of each per SMSP -> tensor pipe 100% packed.
// ============================================================================
template<int NBT>
__device__ void tensor_main(uint32_t sb, int tid, int lane, int wm, int wn) {
    const uint32_t lm_row = (uint32_t)(lane & 15);
    const uint32_t lm_col = (uint32_t)((lane & 16) ? 16 : 0);
    const uint32_t a_lane = ((uint32_t)(wm * 32) + lm_row) * QBUF_RS + lm_col;
    const uint32_t b_lane = sb + SMEM_BANK + ((uint32_t)(wn * 64) + lm_row) * BANK_RS + lm_col;

    int j = 0;
    for (int pass = 0; pass < NPASS; ++pass) {
        uint32_t d[2][2 * NBT][2];
        #pragma unroll
        for (int mt = 0; mt < 2; ++mt)
            #pragma unroll
            for (int nt = 0; nt < 2 * NBT; ++nt) { d[mt][nt][0] = 0u; d[mt][nt][1] = 0u; }

        for (int kc = 0; kc < KCH; ++kc, ++j) {
            const int slot = j % 3;
            if (j == NCHUNK - 1) CP_ASYNC_WAIT(0); else CP_ASYNC_WAIT(1);
            BAR384();
            if (j + 2 < NCHUNK) issue_qchunk(sb, tid, j + 2, (j + 2) % 3);

            const uint32_t abase = sb + (uint32_t)(SMEM_QBUF + slot * QBUF_SZ) + a_lane;
            const uint32_t bbase = b_lane + (uint32_t)(kc * 128);
            #pragma unroll
            for (int ks = 0; ks < 4; ++ks) {
                uint32_t a[2][4];
                #pragma unroll
                for (int mt = 0; mt < 2; ++mt)
                    LDMATRIX_X4(a[mt][0], a[mt][1], a[mt][2], a[mt][3],
                                abase + (uint32_t)(mt * 16 * QBUF_RS + ks * 32));
                #pragma unroll
                for (int bt = 0; bt < NBT; ++bt) {
                    uint32_t b0, b1, b2, b3;
                    LDMATRIX_X4(b0, b1, b2, b3,
                                bbase + (uint32_t)(bt * 16 * BANK_RS + ks * 32));
                    #pragma unroll
                    for (int mt = 0; mt < 2; ++mt) {
                        mma16816h(d[mt][2 * bt],     a[mt], b0, b2);
                        mma16816h(d[mt][2 * bt + 1], a[mt], b1, b3);
                    }
                }
            }
        }

        #pragma unroll
        for (int mt = 0; mt < 2; ++mt) {
            __half2 h0 = u2h2(d[mt][0][0]);
            __half2 h1 = u2h2(d[mt][0][1]);
            #pragma unroll
            for (int nt = 1; nt < 2 * NBT; ++nt) {
                h0 = __hmax2(h0, u2h2(d[mt][nt][0]));
                h1 = __hmax2(h1, u2h2(d[mt][nt][1]));
            }
            float mx0 = fmaxf(__low2float(h0), __high2float(h0));
            float mx1 = fmaxf(__low2float(h1), __high2float(h1));
            mx0 = fmaxf(mx0, __shfl_xor_sync(0xFFFFFFFFu, mx0, 1));
            mx0 = fmaxf(mx0, __shfl_xor_sync(0xFFFFFFFFu, mx0, 2));
            mx1 = fmaxf(mx1, __shfl_xor_sync(0xFFFFFFFFu, mx1, 1));
            mx1 = fmaxf(mx1, __shfl_xor_sync(0xFFFFFFFFu, mx1, 2));
            if ((lane & 3) == 0) {
                int q0 = pass * MEGA + wm * 32 + mt * 16 + (lane >> 2);
                atomicMax(&g_key[q0],     enc_key(mx0));
                atomicMax(&g_key[q0 + 8], enc_key(mx1));
            }
        }
    }
}

// ============================================================================
// FFMA warps: rows 112..127 on the fma pipe. ldmatrix.x4.trans delivers
// half2 = (2 queries @ 1 dim); outer product vs broadcast bank scalars.
// Lane k-split (8 ways, lane>>2) summed by a shuffle tree at pass end.
// NOTE: the query ring slot holds ONLY the current 64-dim chunk — the A
// address must NOT include a kc term (R7 bug: "+ kc*128" walked off smem).
// ============================================================================
__device__ void ffma_main(uint32_t sb, const char* smem_c, int tid) {
    const int lane  = tid & 31;
    const int rw    = (tid >> 5) - 8;                    // 0..3 -> 4 rows each
    const int rbase = TROWS + rw * 4;
    // x4.trans address: matrix f = lane>>3 (dims f*8..f*8+7), row = lane&7
    const uint32_t a_off = (uint32_t)(lane & 7) * QBUF_RS + (uint32_t)(lane >> 3) * 16;
    const int klo = lane >> 2;                           // dim-within-matrix 0..7

    for (int pass = 0; pass < NPASS; ++pass) {
        uint32_t acc[4][16];                             // half2 [row][qblock]
        #pragma unroll
        for (int r = 0; r < 4; ++r)
            #pragma unroll
            for (int qb = 0; qb < 16; ++qb) acc[r][qb] = 0u;

        for (int kc = 0; kc < KCH; ++kc) {
            const int j = pass * KCH + kc;
            const int slot = j % 3;
            if (j == NCHUNK - 1) CP_ASYNC_WAIT(0); else CP_ASYNC_WAIT(1);
            BAR384();
            if (j + 2 < NCHUNK) issue_qchunk(sb, tid, j + 2, (j + 2) % 3);

            // FIX vs R7: slot base only — no kc column offset inside the ring slot.
            const uint32_t abase = sb + (uint32_t)(SMEM_QBUF + slot * QBUF_SZ) + a_off;
            #pragma unroll
            for (int kg = 0; kg < 2; ++kg) {
                const int kbase = kc * 64 + kg * 32;     // dim base in BANK rows
                __half2 bs[4][4];                        // broadcast bank scalars
                #pragma unroll
                for (int r = 0; r < 4; ++r)
                    #pragma unroll
                    for (int f = 0; f < 4; ++f) {
                        const __half hb = *reinterpret_cast<const __half*>(
                            smem_c + (size_t)(rbase + r) * BANK_RS + (kbase + f * 8 + klo) * 2);
                        bs[r][f] = __half2half2(hb);
                    }
                const uint32_t akg = abase + (uint32_t)(kg * 64);
                #pragma unroll
                for (int qb = 0; qb < 16; ++qb) {
                    uint32_t f0, f1, f2, f3;
                    LDMATRIX_X4T(f0, f1, f2, f3, akg + (uint32_t)(qb * 8 * QBUF_RS));
                    const __half2 h0 = u2h2(f0), h1 = u2h2(f1), h2 = u2h2(f2), h3 = u2h2(f3);
                    #pragma unroll
                    for (int r = 0; r < 4; ++r) {
                        __half2 a0 = __hfma2(h0, bs[r][0], u2h2(acc[r][qb]));
                        a0 = __hfma2(h1, bs[r][1], a0);
                        a0 = __hfma2(h2, bs[r][2], a0);
                        a0 = __hfma2(h3, bs[r][3], a0);
                        acc[r][qb] = h22u(a0);
                    }
                }
            }
        }

        // sum k-partials across the 8 k-lanes (xor 4, 8, 16 spans lane>>2)
        #pragma unroll
        for (int r = 0; r < 4; ++r)
            #pragma unroll
            for (int qb = 0; qb < 16; ++qb) {
                uint32_t v = acc[r][qb];
                v = h22u(__hadd2(u2h2(v), u2h2(__shfl_xor_sync(0xFFFFFFFFu, v, 4))));
                v = h22u(__hadd2(u2h2(v), u2h2(__shfl_xor_sync(0xFFFFFFFFu, v, 8))));
                v = h22u(__hadd2(u2h2(v), u2h2(__shfl_xor_sync(0xFFFFFFFFu, v, 16))));
                acc[r][qb] = v;
            }
        if (klo == 0) {                                  // lanes 0..3 own qpairs
            #pragma unroll
            for (int qb = 0; qb < 16; ++qb) {
                __half2 m = __hmax2(__hmax2(u2h2(acc[0][qb]), u2h2(acc[1][qb])),
                                    __hmax2(u2h2(acc[2][qb]), u2h2(acc[3][qb])));
                const int q0 = pass * MEGA + qb * 8 + (lane & 3) * 2;
                atomicMax(&g_key[q0],     enc_key(__low2float(m)));
                atomicMax(&g_key[q0 + 1], enc_key(__high2float(m)));
            }
        }
    }
}

// ============================================================================
// Kernel 2: warp-specialized tensor + FFMA main kernel
// ============================================================================
__global__ void __launch_bounds__(THREADS, 1) patchcore_main(const float* __restrict__ bank) {
    extern __shared__ char smem[];
    const uint32_t sb = smem_to_u32(smem);
    const int tid  = threadIdx.x;
    const int w    = tid >> 5;
    const int lane = tid & 31;
    const size_t m0 = (size_t)blockIdx.x * BANK_TILE;

    // ---- Load bank tile (128 x 512 fp32) -> fp16, padded rows ----
    {
        const float4* src = reinterpret_cast<const float4*>(bank);
        for (int idx = tid; idx < BANK_TILE * (DDIM / 4); idx += THREADS) {
            int m = idx >> 7;
            int c4 = idx & 127;
            float4 v = src[((m0 + (size_t)m) << 7) + c4];
            __half2 lo = __floats2half2_rn(v.x, v.y);
            __half2 hi = __floats2half2_rn(v.z, v.w);
            uint2 p;
            p.x = h22u(lo);
            p.y = h22u(hi);
            *reinterpret_cast<uint2*>(smem + (SMEM_BANK + m * BANK_RS + c4 * 8)) = p;
        }
    }
    issue_qchunk(sb, tid, 0, 0);
    issue_qchunk(sb, tid, 1, 1);
    BAR384();   // bank tile + pipeline primed

    if (w < 8) {
        if ((w >> 2) == 0) tensor_main<4>(sb, tid, lane, w & 3, 0);
        else               tensor_main<3>(sb, tid, lane, w & 3, 1);
    } else {
        ffma_main(sb, smem, tid);
    }
}

// ============================================================================
// Kernel 3: decode keys -> min distances
// ============================================================================
__global__ void final_kernel(float* __restrict__ out) {
    int b = blockIdx.x * blockDim.x + threadIdx.x;
    if (b < NQ) {
        unsigned key = g_key[b];
        unsigned bits = (key & 0x80000000u) ? (key ^ 0x80000000u) : ~key;
        float xy = __uint_as_float(bits);
        out[b] = sqrtf(fmaxf(2.0f - 2.0f * xy, 1e-12f));
    }
}

// ============================================================================
// Launch
// ============================================================================
extern "C" void kernel_launch(void* const* d_in, const int* in_sizes, int n_in,
                              void* d_out, int out_size) {
    const float* feat = (const float*)d_in[0];
    const float* bank = (const float*)d_in[1];
    if (n_in >= 2 && in_sizes[0] != NQ * DDIM) {
        feat = (const float*)d_in[1];
        bank = (const float*)d_in[0];
    }
    float* out = (float*)d_out;

    cudaFuncSetAttribute(patchcore_main, cudaFuncAttributeMaxDynamicSharedMemorySize, SMEM_TOTAL);

    prep_kernel<<<NQ / 4, 128>>>(feat);
    patchcore_main<<<MROWS / BANK_TILE, THREADS, SMEM_TOTAL>>>(bank);
    final_kernel<<<1, NQ>>>(out);
}

// round 10
// speedup vs baseline: 1.6941x; 1.6941x over previous
#include <cuda_runtime.h>
#include <cuda_fp16.h>
#include <cstdint>

// ============================================================================
// Problem constants
// ============================================================================
#define NQ        1024
#define DDIM      512
#define MROWS     262144
#define BANK_TILE 64           // bank rows per CTA (2 CTAs/SM)
#define MEGA      128          // queries per pass
#define NPASS     8
#define KCH       8            // k-chunks of 64 dims per pass
#define NCHUNK    64
#define THREADS   256
#define NCTAS     (MROWS / BANK_TILE)   // 4096
#define PREP_CTAS 128

// smem layout. Row pads: 8-row ldmatrix strides hit distinct 16B groups.
#define BANK_RS    1040
#define QBUF_RS    144
#define SMEM_BANK  0
#define BANK_SZ    (BANK_TILE * BANK_RS)          // 66560
#define SMEM_QBUF  BANK_SZ
#define QBUF_SZ    (MEGA * QBUF_RS)               // 18432
#define SMEM_TOTAL (SMEM_QBUF + 2 * QBUF_SZ)      // 103424 -> 2 CTAs/SM

__device__ __align__(1024) __half g_qh[NQ * DDIM];
__device__ unsigned g_key[NQ];
__device__ volatile unsigned g_prep_done;   // prep-CTA arrival count
__device__ unsigned g_done;                 // finished-CTA count

// ============================================================================
// Helpers
// ============================================================================
__device__ __forceinline__ uint32_t smem_to_u32(const void* p) {
    uint32_t a;
    asm("{ .reg .u64 t; cvta.to.shared.u64 t, %1; cvt.u32.u64 %0, t; }" : "=r"(a) : "l"(p));
    return a;
}

#define CP_ASYNC16(dst_u32, src_gptr) \
    asm volatile("cp.async.cg.shared.global [%0], [%1], 16;" :: "r"(dst_u32), "l"(src_gptr) : "memory")
#define CP_ASYNC_COMMIT() asm volatile("cp.async.commit_group;" ::: "memory")
#define CP_ASYNC_WAIT(n)  asm volatile("cp.async.wait_group %0;" :: "n"(n) : "memory")

#define LDMATRIX_X4(r0, r1, r2, r3, addr) \
    asm volatile("ldmatrix.sync.aligned.m8n8.x4.shared.b16 {%0,%1,%2,%3}, [%4];" \
        : "=r"(r0), "=r"(r1), "=r"(r2), "=r"(r3) : "r"(addr))

__device__ __forceinline__ void mma16816h(uint32_t* d, const uint32_t* a, uint32_t b0, uint32_t b1) {
    asm volatile(
        "mma.sync.aligned.m16n8k16.row.col.f16.f16.f16.f16 "
        "{%0,%1}, {%2,%3,%4,%5}, {%6,%7}, {%0,%1};"
        : "+r"(d[0]), "+r"(d[1])
        : "r"(a[0]), "r"(a[1]), "r"(a[2]), "r"(a[3]), "r"(b0), "r"(b1));
}

__device__ __forceinline__ __half2 u2h2(uint32_t u) { return *reinterpret_cast<__half2*>(&u); }
__device__ __forceinline__ uint32_t h22u(__half2 h) { return *reinterpret_cast<uint32_t*>(&h); }

__device__ __forceinline__ unsigned enc_key(float f) {
    unsigned b = __float_as_uint(f);
    return (b & 0x80000000u) ? ~b : (b | 0x80000000u);
}

// cp.async loader: chunk j = pass*8 + kc (128 queries x 64 fp16 dims) -> slot
__device__ __forceinline__ void issue_qchunk(uint32_t sb, int tid, int j, int slot) {
    const int pass = j >> 3, kc = j & 7;
    const char* src_base = reinterpret_cast<const char*>(g_qh)
                         + (size_t)(pass * MEGA) * (DDIM * 2) + kc * 128;
    const uint32_t dst_base = sb + (uint32_t)(SMEM_QBUF + slot * QBUF_SZ);
    #pragma unroll
    for (int it = 0; it < 4; ++it) {
        int idx = tid + it * THREADS;          // 1024 granules of 16B
        int n = idx >> 3, t = idx & 7;
        CP_ASYNC16(dst_base + (uint32_t)(n * QBUF_RS + t * 16),
                   src_base + (size_t)n * (DDIM * 2) + t * 16);
    }
    CP_ASYNC_COMMIT();
}

// ============================================================================
// Single fused kernel: prep (CTAs 0..127) -> flag -> GEMM+max -> last CTA
// decodes. One launch per call so ncu -s always profiles THIS kernel.
// ============================================================================
__global__ void __launch_bounds__(THREADS, 2)
patchcore_all(const float* __restrict__ feat, const float* __restrict__ bank,
              float* __restrict__ out) {
    extern __shared__ char smem[];
    __shared__ unsigned s_last;
    const uint32_t sb = smem_to_u32(smem);
    const int tid  = threadIdx.x;
    const int w    = tid >> 5;
    const int lane = tid & 31;
    const int wm   = w & 3;        // m-offset wm*32 (queries)
    const int wn   = w >> 2;       // n-offset wn*32 (bank rows)
    const size_t m0 = (size_t)blockIdx.x * BANK_TILE;

    // ---- Bank tile (64 x 512 fp32) -> fp16 smem (independent of queries) ----
    {
        const float4* src = reinterpret_cast<const float4*>(bank);
        #pragma unroll 4
        for (int idx = tid; idx < BANK_TILE * (DDIM / 4); idx += THREADS) {
            int m = idx >> 7;
            int c4 = idx & 127;
            float4 v = src[((m0 + (size_t)m) << 7) + c4];
            uint2 p;
            p.x = h22u(__floats2half2_rn(v.x, v.y));
            p.y = h22u(__floats2half2_rn(v.z, v.w));
            *reinterpret_cast<uint2*>(smem + (SMEM_BANK + m * BANK_RS + c4 * 8)) = p;
        }
    }

    // ---- Prep: CTAs 0..127 normalize 8 queries each (warp per query) ----
    if (blockIdx.x < PREP_CTAS) {
        const int q = blockIdx.x * 8 + w;
        const float4* src = reinterpret_cast<const float4*>(feat + (size_t)q * DDIM);
        float4 v[4];
        float ss = 0.0f;
        #pragma unroll
        for (int p = 0; p < 4; ++p) {
            v[p] = src[p * 32 + lane];
            ss += v[p].x * v[p].x + v[p].y * v[p].y + v[p].z * v[p].z + v[p].w * v[p].w;
        }
        #pragma unroll
        for (int o = 16; o > 0; o >>= 1) ss += __shfl_xor_sync(0xFFFFFFFFu, ss, o);
        const float inv = rsqrtf(ss);
        __half2* dst = reinterpret_cast<__half2*>(g_qh + (size_t)q * DDIM);
        #pragma unroll
        for (int p = 0; p < 4; ++p) {
            dst[(p * 32 + lane) * 2 + 0] = __floats2half2_rn(v[p].x * inv, v[p].y * inv);
            dst[(p * 32 + lane) * 2 + 1] = __floats2half2_rn(v[p].z * inv, v[p].w * inv);
        }
        if (lane == 0) g_key[q] = 0u;
        __syncthreads();
        if (tid == 0) {
            __threadfence();                        // release g_qh/g_key
            atomicAdd((unsigned*)&g_prep_done, 1u);
        }
    }

    // ---- Acquire: wait for all prep CTAs (wave 1 holds them all) ----
    if (tid == 0) {
        while (g_prep_done < PREP_CTAS) __nanosleep(64);
        __threadfence();                            // acquire
    }
    __syncthreads();                                // also orders bank smem stores

    // ---- Main GEMM loop: ring-2 query buffer, one barrier per chunk ----
    const uint32_t lm_row = (uint32_t)(lane & 15);
    const uint32_t lm_col = (uint32_t)((lane & 16) ? 16 : 0);
    const uint32_t a_lane = ((uint32_t)(wm * 32) + lm_row) * QBUF_RS + lm_col;
    const uint32_t b_lane = sb + SMEM_BANK + ((uint32_t)(wn * 32) + lm_row) * BANK_RS + lm_col;

    issue_qchunk(sb, tid, 0, 0);
    int j = 0;
    for (int pass = 0; pass < NPASS; ++pass) {
        uint32_t d[2][4][2];                        // [m-tile][n8-tile][row] f16x2
        #pragma unroll
        for (int mt = 0; mt < 2; ++mt)
            #pragma unroll
            for (int nt = 0; nt < 4; ++nt) { d[mt][nt][0] = 0u; d[mt][nt][1] = 0u; }

        for (int kc = 0; kc < KCH; ++kc, ++j) {
            CP_ASYNC_WAIT(0);                       // chunk j landed
            __syncthreads();                        // all warps done with slot j^1
            if (j + 1 < NCHUNK) issue_qchunk(sb, tid, j + 1, (j + 1) & 1);

            const uint32_t abase = sb + (uint32_t)(SMEM_QBUF + (j & 1) * QBUF_SZ) + a_lane;
            const uint32_t bbase = b_lane + (uint32_t)(kc * 128);
            #pragma unroll
            for (int ks = 0; ks < 4; ++ks) {
                uint32_t a[2][4];
                #pragma unroll
                for (int mt = 0; mt < 2; ++mt)
                    LDMATRIX_X4(a[mt][0], a[mt][1], a[mt][2], a[mt][3],
                                abase + (uint32_t)(mt * 16 * QBUF_RS + ks * 32));
                #pragma unroll
                for (int bt = 0; bt < 2; ++bt) {
                    uint32_t b0, b1, b2, b3;        // b0/b2: n8 tile 2bt ; b1/b3: 2bt+1
                    LDMATRIX_X4(b0, b1, b2, b3,
                                bbase + (uint32_t)(bt * 16 * BANK_RS + ks * 32));
                    #pragma unroll
                    for (int mt = 0; mt < 2; ++mt) {
                        mma16816h(d[mt][2 * bt],     a[mt], b0, b2);
                        mma16816h(d[mt][2 * bt + 1], a[mt], b1, b3);
                    }
                }
            }
        }

        // ---- Epilogue: max over this warp's 32 bank rows per query ----
        #pragma unroll
        for (int mt = 0; mt < 2; ++mt) {
            __half2 h0 = u2h2(d[mt][0][0]);
            __half2 h1 = u2h2(d[mt][0][1]);
            #pragma unroll
            for (int nt = 1; nt < 4; ++nt) {
                h0 = __hmax2(h0, u2h2(d[mt][nt][0]));
                h1 = __hmax2(h1, u2h2(d[mt][nt][1]));
            }
            float mx0 = fmaxf(__low2float(h0), __high2float(h0));
            float mx1 = fmaxf(__low2float(h1), __high2float(h1));
            mx0 = fmaxf(mx0, __shfl_xor_sync(0xFFFFFFFFu, mx0, 1));
            mx0 = fmaxf(mx0, __shfl_xor_sync(0xFFFFFFFFu, mx0, 2));
            mx1 = fmaxf(mx1, __shfl_xor_sync(0xFFFFFFFFu, mx1, 1));
            mx1 = fmaxf(mx1, __shfl_xor_sync(0xFFFFFFFFu, mx1, 2));
            if ((lane & 3) == 0) {
                int q0 = pass * MEGA + wm * 32 + mt * 16 + (lane >> 2);
                atomicMax(&g_key[q0],     enc_key(mx0));
                atomicMax(&g_key[q0 + 8], enc_key(mx1));
            }
        }
    }

    // ---- Completion: last CTA decodes keys and resets counters ----
    __threadfence();                                // release atomicMax results
    __syncthreads();
    if (tid == 0) s_last = atomicAdd(&g_done, 1u);
    __syncthreads();
    if (s_last == NCTAS - 1) {
        __threadfence();                            // acquire all g_key updates
        volatile unsigned* keys = (volatile unsigned*)g_key;
        for (int i = tid; i < NQ; i += THREADS) {
            unsigned key = keys[i];
            unsigned bits = (key & 0x80000000u) ? (key ^ 0x80000000u) : ~key;
            float xy = __uint_as_float(bits);
            out[i] = sqrtf(fmaxf(2.0f - 2.0f * xy, 1e-12f));
        }
        __syncthreads();
        if (tid == 0) {                             // reset for next graph replay
            g_done = 0;
            *(unsigned*)&g_prep_done = 0;
        }
    }
}

// ============================================================================
// Launch: one kernel
// ============================================================================
extern "C" void kernel_launch(void* const* d_in, const int* in_sizes, int n_in,
                              void* d_out, int out_size) {
    const float* feat = (const float*)d_in[0];
    const float* bank = (const float*)d_in[1];
    if (n_in >= 2 && in_sizes[0] != NQ * DDIM) {   // robust to input ordering
        feat = (const float*)d_in[1];
        bank = (const float*)d_in[0];
    }
    float* out = (float*)d_out;

    cudaFuncSetAttribute(patchcore_all, cudaFuncAttributeMaxDynamicSharedMemorySize, SMEM_TOTAL);
    patchcore_all<<<NCTAS, THREADS, SMEM_TOTAL>>>(feat, bank, out);
}